// round 17
// baseline (speedup 1.0000x reference)
#include <cuda_runtime.h>
#include <math.h>

#define DM 1024
#define DF 4096
#define NE 8
#define NSLOT 16
#define BB 4
#define TT 4096
#define BT (BB*TT)
#define NCHUNK 64           // 64-token chunks per batch
#define CT 64               // tokens per chunk
#define KSPLIT 8            // k5: d-chunks of 128
#define FSPLIT 32           // k5b: f-chunks of 128

typedef unsigned long long u64t;

// ---- packed f32x2 helpers (sm_103a FFMA2 path; fp32-exact) ----
__device__ __forceinline__ u64t pk2(float a, float b) {
    u64t r; asm("mov.b64 %0, {%1, %2};" : "=l"(r) : "f"(a), "f"(b)); return r;
}
__device__ __forceinline__ u64t dup2f(float a) {
    u64t r; asm("mov.b64 %0, {%1, %1};" : "=l"(r) : "f"(a)); return r;
}
__device__ __forceinline__ void fma2(u64t& d, u64t a, u64t b) {
    asm("fma.rn.f32x2 %0, %1, %2, %0;" : "+l"(d) : "l"(a), "l"(b));
}
__device__ __forceinline__ float2 upk(u64t v) {
    float2 r; asm("mov.b64 {%0, %1}, %2;" : "=f"(r.x), "=f"(r.y) : "l"(v)); return r;
}

// ---- cp.async helpers ----
__device__ __forceinline__ void cp16(void* smem_dst, const void* gsrc) {
    unsigned s = (unsigned)__cvta_generic_to_shared(smem_dst);
    asm volatile("cp.async.cg.shared.global [%0], [%1], 16;" :: "r"(s), "l"(gsrc));
}
#define CP_COMMIT() asm volatile("cp.async.commit_group;")
#define CP_WAIT2()  asm volatile("cp.async.wait_group 2;" ::: "memory")

// ---------------- scratch (device globals, no allocation) ----------------
__device__ float g_logits[BT * NSLOT];                 // 1 MB
__device__ float g_csum_p[BB * NCHUNK * NSLOT];
__device__ float g_psum[BB * NCHUNK * NSLOT * DM];     // 16 MB  [b*64+tc][n][d]
__device__ float g_si[NE * DM * 8];                    // 256 KB [e][d][m]
__device__ float g_s1[64 * 4];
__device__ float g_s2[64 * 4];
__device__ float g_mean[NE * 8];
__device__ float g_rstd[NE * 8];
__device__ float g_pu[KSPLIT * NE * DF * 8];           // 8 MB   [ks][e][f][m]
__device__ float g_pso[FSPLIT * NE * DM * 8];          // 8 MB   [fs][e][d][m]
__device__ float g_so[BB * NSLOT * DM];                // 256 KB [b][n][d]

// ---------------- K13: fused logits + dispatch-softmax weighted sums ----------------
__global__ __launch_bounds__(256) void k13_fused(const float* __restrict__ x,
                                                 const float* __restrict__ se) {
    __shared__ float xs[CT * 65];        // [64 tok][65] padded
    __shared__ float ss[NSLOT * 65];     // [16 slot][65] padded
    __shared__ float ls[CT * NSLOT];
    __shared__ float ws[CT * NSLOT];
    int tid = threadIdx.x;
    int tc = blockIdx.x, b = blockIdx.y;
    int t0 = tc * CT;
    const float* xb = x + (size_t)(b * TT + t0) * DM;

    int pos = tid >> 2, q = tid & 3;     // 64 positions x 4 d-quarters
    int tokg = pos >> 2, slotg = pos & 3;
    u64t accp1[4][2];
#pragma unroll
    for (int i = 0; i < 4; i++) { accp1[i][0] = 0ull; accp1[i][1] = 0ull; }

    for (int dt = 0; dt < DM; dt += 64) {
#pragma unroll
        for (int r = 0; r < 4; r++) {
            int idx = tid + 256 * r;
            int n = idx >> 6, dd2 = idx & 63;
            ss[n * 65 + dd2] = se[(size_t)n * DM + dt + dd2];
        }
#pragma unroll
        for (int r = 0; r < 4; r++) {
            int idx = tid + 256 * r;
            int t = idx >> 4, dq = idx & 15;
            float4 v = *(const float4*)(xb + (size_t)t * DM + dt + dq * 4);
            float* p = xs + t * 65 + dq * 4;
            p[0] = v.x; p[1] = v.y; p[2] = v.z; p[3] = v.w;
        }
        __syncthreads();
#pragma unroll
        for (int dd = 0; dd < 16; dd++) {
            int d = dd * 4 + q;
            u64t svp0 = pk2(ss[(slotg * 4 + 0) * 65 + d], ss[(slotg * 4 + 1) * 65 + d]);
            u64t svp1 = pk2(ss[(slotg * 4 + 2) * 65 + d], ss[(slotg * 4 + 3) * 65 + d]);
            u64t x0 = dup2f(xs[(tokg * 4 + 0) * 65 + d]);
            u64t x1 = dup2f(xs[(tokg * 4 + 1) * 65 + d]);
            u64t x2 = dup2f(xs[(tokg * 4 + 2) * 65 + d]);
            u64t x3 = dup2f(xs[(tokg * 4 + 3) * 65 + d]);
            fma2(accp1[0][0], x0, svp0); fma2(accp1[0][1], x0, svp1);
            fma2(accp1[1][0], x1, svp0); fma2(accp1[1][1], x1, svp1);
            fma2(accp1[2][0], x2, svp0); fma2(accp1[2][1], x2, svp1);
            fma2(accp1[3][0], x3, svp0); fma2(accp1[3][1], x3, svp1);
        }
        __syncthreads();
    }
#pragma unroll
    for (int i = 0; i < 4; i++)
#pragma unroll
        for (int jp = 0; jp < 2; jp++) {
            float2 v = upk(accp1[i][jp]);
            v.x += __shfl_xor_sync(0xFFFFFFFFu, v.x, 1);
            v.x += __shfl_xor_sync(0xFFFFFFFFu, v.x, 2);
            v.y += __shfl_xor_sync(0xFFFFFFFFu, v.y, 1);
            v.y += __shfl_xor_sync(0xFFFFFFFFu, v.y, 2);
            if (q == 0) {
                ls[(tokg * 4 + i) * 16 + slotg * 4 + jp * 2 + 0] = v.x * 0.03125f;
                ls[(tokg * 4 + i) * 16 + slotg * 4 + jp * 2 + 1] = v.y * 0.03125f;
            }
        }
    __syncthreads();

    float* lg = g_logits + (size_t)(b * TT + t0) * NSLOT;
#pragma unroll
    for (int r = 0; r < 4; r++) {
        int idx = tid + 256 * r;
        float l = ls[idx];
        lg[idx] = l;
        ws[idx] = expf(l);
    }
    __syncthreads();

    if (tid < 16) {
        float s = 0.f;
        for (int t = 0; t < CT; t++) s += ws[t * 16 + tid];
        g_csum_p[(b * NCHUNK + tc) * 16 + tid] = s;
    }

    u64t accp2[16][2];
#pragma unroll
    for (int n = 0; n < 16; n++) { accp2[n][0] = 0ull; accp2[n][1] = 0ull; }
    const float* xp = xb + tid * 4;
    float4 xn0 = *(const float4*)xp;
    float4 xn1 = *(const float4*)(xp + DM);
#pragma unroll 1
    for (int t = 0; t < CT; t++) {
        float4 xv = xn0;
        xn0 = xn1;
        if (t + 2 < CT) xn1 = *(const float4*)(xp + (size_t)(t + 2) * DM);
        u64t xl = pk2(xv.x, xv.y), xh = pk2(xv.z, xv.w);
#pragma unroll
        for (int n = 0; n < 16; n++) {
            u64t wd = dup2f(ws[t * 16 + n]);
            fma2(accp2[n][0], xl, wd);
            fma2(accp2[n][1], xh, wd);
        }
    }
    float* op = g_psum + (size_t)(b * NCHUNK + tc) * 16 * DM + tid * 4;
#pragma unroll
    for (int n = 0; n < 16; n++) {
        float2 a = upk(accp2[n][0]), c = upk(accp2[n][1]);
        *(float4*)(op + (size_t)n * DM) = make_float4(a.x, a.y, c.x, c.y);
    }
}

// ---------------- K4a: reduce partials, normalize, transpose, partial LN stats ----
__global__ __launch_bounds__(256) void k4a_reduce() {
    __shared__ float red[256];
    int bn = blockIdx.x, dc = blockIdx.y;
    int b = bn >> 4, n = bn & 15;
    int tid = threadIdx.x;
    if (tid < NCHUNK) red[tid] = g_csum_p[(b * NCHUNK + tid) * 16 + n];
    __syncthreads();
    if (tid == 0) {
        float s = 0.f;
        for (int i = 0; i < NCHUNK; i++) s += red[i];
        red[0] = 1.0f / s;
    }
    __syncthreads();
    float inv = red[0];
    __syncthreads();

    int d = dc * 256 + tid;
    const float* pp = g_psum + ((size_t)(b * NCHUNK) * 16 + n) * DM + d;
    float va = 0.f, vb = 0.f;
#pragma unroll 4
    for (int t = 0; t < NCHUNK; t += 2) {
        va += pp[(size_t)t * 16 * DM];
        vb += pp[(size_t)(t + 1) * 16 * DM];
    }
    float v = (va + vb) * inv;
    int e = n >> 1, sl = n & 1, m = (b << 1) | sl;
    g_si[((size_t)e * DM + d) * 8 + m] = v;

    red[tid] = v; __syncthreads();
    for (int s = 128; s > 0; s >>= 1) {
        if (tid < s) red[tid] += red[tid + s];
        __syncthreads();
    }
    float s1 = red[0]; __syncthreads();
    red[tid] = v * v; __syncthreads();
    for (int s = 128; s > 0; s >>= 1) {
        if (tid < s) red[tid] += red[tid + s];
        __syncthreads();
    }
    if (tid == 0) { g_s1[bn * 4 + dc] = s1; g_s2[bn * 4 + dc] = red[0]; }
}

// ---------------- K4b: finalize LN stats ----------------
__global__ void k4b_stats() {
    int bn = threadIdx.x;
    if (bn < 64) {
        float s1 = 0.f, s2 = 0.f;
#pragma unroll
        for (int q = 0; q < 4; q++) { s1 += g_s1[bn * 4 + q]; s2 += g_s2[bn * 4 + q]; }
        float mean = s1 * (1.0f / DM);
        float var = fmaxf(s2 * (1.0f / DM) - mean * mean, 0.f);
        int b = bn >> 4, n = bn & 15;
        int e = n >> 1, m = (b << 1) | (n & 1);
        g_mean[e * 8 + m] = mean;
        g_rstd[e * 8 + m] = rsqrtf(var + 1e-5f);
    }
}

// Packed consume: one weight row (4 cols) x 4 m rows = 8 f32x2 FMA
#define CONSUME1P(ACCP, S, ROW, MH, W) { \
    float4 _h = *(const float4*)((S) + (ROW) * 8 + (MH) * 4); \
    u64t _hl = pk2(_h.x, _h.y), _hh = pk2(_h.z, _h.w); \
    u64t _w0 = dup2f(W.x), _w1 = dup2f(W.y), _w2 = dup2f(W.z), _w3 = dup2f(W.w); \
    fma2(ACCP[0][0], _hl, _w0); fma2(ACCP[1][0], _hh, _w0); \
    fma2(ACCP[0][1], _hl, _w1); fma2(ACCP[1][1], _hh, _w1); \
    fma2(ACCP[0][2], _hl, _w2); fma2(ACCP[1][2], _hh, _w2); \
    fma2(ACCP[0][3], _hl, _w3); fma2(ACCP[1][3], _hh, _w3); }

// ---------------- K5: GEMM1 pu[ks][e][f][m] = LN(si) . W1 ----------------
// grid (fc=8, e=8, ks=8) = 512 blocks, block 256.
// 3-stage cp.async ring: 16 KB tiles, 2 tiles in flight while consuming one.
__global__ __launch_bounds__(256) void k5_gemm1(const float* __restrict__ W1,
                                                const float* __restrict__ gamma,
                                                const float* __restrict__ beta) {
    __shared__ float hs[128 * 8];
    __shared__ __align__(16) float wt[3][8 * 512];   // 48 KB
    int tid = threadIdx.x;
    int fc = blockIdx.x, e = blockIdx.y, ks = blockIdx.z;
    {   // stage 128 d x 8 m with LN applied
        int d = ks * 128 + (tid >> 1);
        int mb = (tid & 1) * 4;
        float4 v = *(const float4*)(g_si + ((size_t)e * DM + d) * 8 + mb);
        float4 mu = *(const float4*)(g_mean + e * 8 + mb);
        float4 rs = *(const float4*)(g_rstd + e * 8 + mb);
        float ga = gamma[d], be = beta[d];
        v.x = (v.x - mu.x) * rs.x * ga + be;
        v.y = (v.y - mu.y) * rs.y * ga + be;
        v.z = (v.z - mu.z) * rs.z * ga + be;
        v.w = (v.w - mu.w) * rs.w * ga + be;
        *(float4*)(hs + tid * 4) = v;
    }
    int mh = tid >> 7;
    int fsl = tid & 127;
    const float* wbase = W1 + ((size_t)e * DM + ks * 128) * DF + fc * 512;

    int r0 = tid >> 7;            // this thread's row pair base (0/1)
    int c0 = tid & 127;           // col slot
    // prologue: issue tiles 0 and 1 as separate groups
#pragma unroll
    for (int t = 0; t < 2; t++) {
#pragma unroll
        for (int i = 0; i < 4; i++) {
            int row = r0 + i * 2;
            cp16(&wt[t][row * 512 + c0 * 4],
                 wbase + (size_t)(t * 8 + row) * DF + c0 * 4);
        }
        CP_COMMIT();
    }

    u64t accp[2][4];
#pragma unroll
    for (int i = 0; i < 2; i++)
#pragma unroll
        for (int j = 0; j < 4; j++) accp[i][j] = 0ull;

#pragma unroll 1
    for (int c = 0; c < 16; c++) {
        if (c + 2 < 16) {
            float* dst = wt[(c + 2) % 3];
            const float* src = wbase + (size_t)(c + 2) * 8 * DF;
#pragma unroll
            for (int i = 0; i < 4; i++) {
                int row = r0 + i * 2;
                cp16(&dst[row * 512 + c0 * 4], src + (size_t)row * DF + c0 * 4);
            }
        }
        CP_COMMIT();
        CP_WAIT2();
        __syncthreads();
        const float* wts = wt[c % 3];
#pragma unroll
        for (int r = 0; r < 8; r++) {
            float4 w = *(const float4*)(wts + r * 512 + fsl * 4);
            CONSUME1P(accp, hs, c * 8 + r, mh, w)
        }
        __syncthreads();
    }
    int f0 = fc * 512 + fsl * 4;
    float* op = g_pu + ((size_t)(ks * NE + e) * DF + f0) * 8 + mh * 4;
#pragma unroll
    for (int j = 0; j < 4; j++) {
        float2 p0 = upk(accp[0][j]), p1 = upk(accp[1][j]);
        *(float4*)(op + j * 8) = make_float4(p0.x, p0.y, p1.x, p1.y);
    }
}

__device__ __forceinline__ float gelu_exact(float v) {
    return 0.5f * v * (1.0f + erff(v * 0.70710678118654752f));
}

// ---------------- K5b: GEMM2 pso[fs][e][d][m] = gelu(sum pu) . W2 ----------------
// grid (dc=2, e=8, fs=32) = 512 blocks; same 3-stage cp.async ring.
__global__ __launch_bounds__(256) void k5b_gemm2(const float* __restrict__ W2) {
    __shared__ float us[128 * 8];
    __shared__ __align__(16) float wt[3][8 * 512];   // 48 KB
    int tid = threadIdx.x;
    int dc = blockIdx.x, e = blockIdx.y, fs = blockIdx.z;
    {   // stage u = gelu(sum of 8 k-split partials)
        int f = fs * 128 + (tid >> 1);
        int mb = (tid & 1) * 4;
        const float* pp = g_pu + ((size_t)e * DF + f) * 8 + mb;
        float4 s = *(const float4*)pp;
#pragma unroll
        for (int kq = 1; kq < KSPLIT; kq++) {
            float4 v = *(const float4*)(pp + (size_t)kq * NE * DF * 8);
            s.x += v.x; s.y += v.y; s.z += v.z; s.w += v.w;
        }
        float4 g;
        g.x = gelu_exact(s.x); g.y = gelu_exact(s.y);
        g.z = gelu_exact(s.z); g.w = gelu_exact(s.w);
        *(float4*)(us + tid * 4) = g;
    }
    int mh = tid >> 7;
    int dsl = tid & 127;
    const float* wbase = W2 + ((size_t)e * DF + fs * 128) * DM + dc * 512;

    int r0 = tid >> 7;
    int c0 = tid & 127;
#pragma unroll
    for (int t = 0; t < 2; t++) {
#pragma unroll
        for (int i = 0; i < 4; i++) {
            int row = r0 + i * 2;
            cp16(&wt[t][row * 512 + c0 * 4],
                 wbase + (size_t)(t * 8 + row) * DM + c0 * 4);
        }
        CP_COMMIT();
    }

    u64t accp[2][4];
#pragma unroll
    for (int i = 0; i < 2; i++)
#pragma unroll
        for (int j = 0; j < 4; j++) accp[i][j] = 0ull;

#pragma unroll 1
    for (int c = 0; c < 16; c++) {
        if (c + 2 < 16) {
            float* dst = wt[(c + 2) % 3];
            const float* src = wbase + (size_t)(c + 2) * 8 * DM;
#pragma unroll
            for (int i = 0; i < 4; i++) {
                int row = r0 + i * 2;
                cp16(&dst[row * 512 + c0 * 4], src + (size_t)row * DM + c0 * 4);
            }
        }
        CP_COMMIT();
        CP_WAIT2();
        __syncthreads();
        const float* wts = wt[c % 3];
#pragma unroll
        for (int r = 0; r < 8; r++) {
            float4 w = *(const float4*)(wts + r * 512 + dsl * 4);
            CONSUME1P(accp, us, c * 8 + r, mh, w)
        }
        __syncthreads();
    }
    int d0 = dc * 512 + dsl * 4;
    float* op = g_pso + ((size_t)(fs * NE + e) * DM + d0) * 8 + mh * 4;
#pragma unroll
    for (int j = 0; j < 4; j++) {
        float2 p0 = upk(accp[0][j]), p1 = upk(accp[1][j]);
        *(float4*)(op + j * 8) = make_float4(p0.x, p0.y, p1.x, p1.y);
    }
}

// ---------------- K5c: reduce 32 f-split partials -> slot_out[b][n][d] ----------------
__global__ __launch_bounds__(128) void k5c_reduce() {
    int idx = blockIdx.x * 128 + threadIdx.x;  // 0..16383
    int e = idx >> 11;
    int rest = idx & 2047;
    int d = rest >> 1, mh = rest & 1;
    const float* pp = g_pso + ((size_t)e * DM + d) * 8 + mh * 4;
    float4 a = *(const float4*)pp;
#pragma unroll 8
    for (int fs = 1; fs < FSPLIT; fs++) {
        float4 v = *(const float4*)(pp + (size_t)fs * NE * DM * 8);
        a.x += v.x; a.y += v.y; a.z += v.z; a.w += v.w;
    }
    int m0 = mh * 4;
    float vals[4] = {a.x, a.y, a.z, a.w};
#pragma unroll
    for (int j = 0; j < 4; j++) {
        int m = m0 + j;
        int b = m >> 1, sl = m & 1;
        g_so[(size_t)(b * 16 + e * 2 + sl) * DM + d] = vals[j];
    }
}

// ---------------- K6: combine = softmax_n(logits) @ slot_out ----------------
__global__ __launch_bounds__(256) void k6_combine(float* __restrict__ out) {
    __shared__ float cs[64 * 16];
    int tc = blockIdx.x, b = blockIdx.y;
    int tid = threadIdx.x;
    int t0 = tc * 64;
    if (tid < 64) {
        const float* lp = g_logits + (size_t)(b * TT + t0 + tid) * NSLOT;
        float l[16];
#pragma unroll
        for (int n = 0; n < 16; n++) l[n] = lp[n];
        float m = l[0];
#pragma unroll
        for (int n = 1; n < 16; n++) m = fmaxf(m, l[n]);
        float sum = 0.f;
#pragma unroll
        for (int n = 0; n < 16; n++) { l[n] = expf(l[n] - m); sum += l[n]; }
        float inv = 1.0f / sum;
#pragma unroll
        for (int n = 0; n < 16; n++) cs[tid * 16 + n] = l[n] * inv;
    }
    __syncthreads();
    u64t svp[16][2];
    const float* sp = g_so + (size_t)b * 16 * DM + tid * 4;
#pragma unroll
    for (int n = 0; n < 16; n++) {
        float4 v = *(const float4*)(sp + (size_t)n * DM);
        svp[n][0] = pk2(v.x, v.y);
        svp[n][1] = pk2(v.z, v.w);
    }
    float* op = out + (size_t)(b * TT + t0) * DM + tid * 4;
    for (int t = 0; t < 64; t++) {
        u64t a0 = 0ull, a1 = 0ull;
#pragma unroll
        for (int n = 0; n < 16; n++) {
            u64t cd = dup2f(cs[t * 16 + n]);
            fma2(a0, svp[n][0], cd);
            fma2(a1, svp[n][1], cd);
        }
        float2 p0 = upk(a0), p1 = upk(a1);
        *(float4*)(op + (size_t)t * DM) = make_float4(p0.x, p0.y, p1.x, p1.y);
    }
}

// ---------------- launch ----------------
extern "C" void kernel_launch(void* const* d_in, const int* in_sizes, int n_in,
                              void* d_out, int out_size) {
    const float* x     = (const float*)d_in[0];
    const float* se    = (const float*)d_in[1];
    const float* W1    = (const float*)d_in[2];
    const float* W2    = (const float*)d_in[3];
    const float* gamma = (const float*)d_in[4];
    const float* beta  = (const float*)d_in[5];
    float* out = (float*)d_out;

    { dim3 g(NCHUNK, BB);        k13_fused<<<g, 256>>>(x, se); }
    { dim3 g(64, 4);             k4a_reduce<<<g, 256>>>(); }
    k4b_stats<<<1, 64>>>();
    { dim3 g(8, NE, KSPLIT);     k5_gemm1<<<g, 256>>>(W1, gamma, beta); }
    { dim3 g(2, NE, FSPLIT);     k5b_gemm2<<<g, 256>>>(W2); }
    k5c_reduce<<<128, 128>>>();
    { dim3 g(64, BB);            k6_combine<<<g, 256>>>(out); }
}